// round 11
// baseline (speedup 1.0000x reference)
#include <cuda_runtime.h>

#define N_LAYERS 32
#define N_BLK    16          // fused 2-layer blocks per chain
#define N_SUB    8
#define TPB      64
#define EPT      6

__device__ __forceinline__ float tanh_fast(float x) {
    float y;
    asm("tanh.approx.f32 %0, %1;" : "=f"(y) : "f"(x));
    return y;
}

// Compose layer i's (bias then 8 shears) into forward affine v' = M v + c.
__device__ __forceinline__ void compose_fwd(const float* bias_b, const float* lin_w,
                                            int i, float M[4], float c[2]) {
    float m00 = 1.f, m01 = 0.f, m10 = 0.f, m11 = 1.f;
    float c0 = bias_b[2 * i + 0];
    float c1 = bias_b[2 * i + 1];
    #pragma unroll
    for (int j = 0; j < N_SUB; ++j) {
        float w = lin_w[i * N_SUB + j];
        if ((j & 1) == 0) {          // q += w*p
            m00 = fmaf(w, m10, m00);
            m01 = fmaf(w, m11, m01);
            c0  = fmaf(w, c1,  c0);
        } else {                      // p += w*q
            m10 = fmaf(w, m00, m10);
            m11 = fmaf(w, m01, m11);
            c1  = fmaf(w, c0,  c1);
        }
    }
    M[0] = m00; M[1] = m01; M[2] = m10; M[3] = m11;
    c[0] = c0;  c[1] = c1;
}

// Inverse affine of layer i: v = U w + d (reversed negated shears; d = -bias).
__device__ __forceinline__ void compose_inv(const float* bias_b, const float* lin_w,
                                            int i, float U[4], float d[2]) {
    float u00 = 1.f, u01 = 0.f, u10 = 0.f, u11 = 1.f;
    #pragma unroll
    for (int j = N_SUB - 1; j >= 0; --j) {
        float w = lin_w[i * N_SUB + j];
        if ((j & 1) == 0) {          // q -= w*p
            u00 = fmaf(-w, u10, u00);
            u01 = fmaf(-w, u11, u01);
        } else {                      // p -= w*q
            u10 = fmaf(-w, u00, u10);
            u11 = fmaf(-w, u01, u11);
        }
    }
    U[0] = u00; U[1] = u01; U[2] = u10; U[3] = u11;
    d[0] = -bias_b[2 * i + 0];
    d[1] = -bias_b[2 * i + 1];
}

__global__ __launch_bounds__(TPB, 20)
void sympnet_kernel(const float2* __restrict__ x,
                    const float*  __restrict__ act_w,
                    const float*  __restrict__ bias_b,
                    const float*  __restrict__ lin_w,
                    float2*       __restrict__ out,
                    int n)
{
    // Fused 2-layer block constants (3 x float4 each):
    // fwd[k]: [0]={a_e, Me00, Me01, ce0}  [1]={A00,A01,b0,ah0}  [2]={A10,A11,b1,ah1}
    // inv[k]: [0]={Uo00, Uo01, do0, -a_e} [1]={B00,B01,e0,ch0}  [2]={B10,B11,e1,ch1}
    // Sign folds: k=N_BLK-1 absorbs the time-reversal p -> -p (negated .y coeffs);
    //             k=0 absorbs the final (q, -p) output (negated np row + ia.w).
    __shared__ float4 s_fb[N_BLK][3];
    __shared__ float4 s_ib[N_BLK][3];

    const int t = threadIdx.x;

    if (t < N_BLK) {
        const int k = t, i = 2 * k;
        float Me[4], ce[2], Mo[4], co[2];
        compose_fwd(bias_b, lin_w, i,     Me, ce);
        compose_fwd(bias_b, lin_w, i + 1, Mo, co);
        float a_e = act_w[i], a_o = act_w[i + 1];
        // A = Mo * Me ; b = Mo*ce + co ; ah = a_o * (Mo col-p)
        float A00 = Mo[0] * Me[0] + Mo[1] * Me[2];
        float A01 = Mo[0] * Me[1] + Mo[1] * Me[3];
        float A10 = Mo[2] * Me[0] + Mo[3] * Me[2];
        float A11 = Mo[2] * Me[1] + Mo[3] * Me[3];
        float b0  = Mo[0] * ce[0] + Mo[1] * ce[1] + co[0];
        float b1  = Mo[2] * ce[0] + Mo[3] * ce[1] + co[1];
        float ah0 = a_o * Mo[1];
        float ah1 = a_o * Mo[3];
        s_fb[k][0] = make_float4(a_e, Me[0], Me[1], ce[0]);
        s_fb[k][1] = make_float4(A00, A01, b0, ah0);
        s_fb[k][2] = make_float4(A10, A11, b1, ah1);
    } else if (t < 2 * N_BLK) {
        const int k = t - N_BLK, i = 2 * k;
        float Ue[4], de[2], Uo[4], dd[2];
        compose_inv(bias_b, lin_w, i,     Ue, de);
        compose_inv(bias_b, lin_w, i + 1, Uo, dd);
        float a_e = act_w[i], a_o = act_w[i + 1];
        // B = Ue * Uo ; e = Ue*do + de ; ch = -a_o * (Ue col-p)
        float B00 = Ue[0] * Uo[0] + Ue[1] * Uo[2];
        float B01 = Ue[0] * Uo[1] + Ue[1] * Uo[3];
        float B10 = Ue[2] * Uo[0] + Ue[3] * Uo[2];
        float B11 = Ue[2] * Uo[1] + Ue[3] * Uo[3];
        float e0  = Ue[0] * dd[0] + Ue[1] * dd[1] + de[0];
        float e1  = Ue[2] * dd[0] + Ue[3] * dd[1] + de[1];
        float ch0 = -a_o * Ue[1];
        float ch1 = -a_o * Ue[3];
        // sy: fold time-reversal (-p) into entry block (k = N_BLK-1)
        // so: fold final (-p) output into exit block (k = 0)
        float sy = (k == N_BLK - 1) ? -1.f : 1.f;
        float so = (k == 0)         ? -1.f : 1.f;
        s_ib[k][0] = make_float4(Uo[0], sy * Uo[1], dd[0], so * -a_e);
        s_ib[k][1] = make_float4(B00, sy * B01, e0, ch0);
        s_ib[k][2] = make_float4(so * B10, so * sy * B11, so * e1, so * ch1);
    }
    __syncthreads();

    const int base = blockIdx.x * (TPB * EPT) + t;

    float q[EPT], p[EPT];
    #pragma unroll
    for (int e = 0; e < EPT; ++e) {
        int idx = base + e * TPB;
        if (idx < n) {
            float2 v = x[idx];
            q[e] = v.x; p[e] = v.y;
        } else {
            q[e] = 0.f; p[e] = 0.f;
        }
    }

    // ---------------- forward chain: 16 fused blocks ----------------
    #pragma unroll 4
    for (int k = 0; k < N_BLK; ++k) {
        float4 fa = s_fb[k][0];
        float4 fb = s_fb[k][1];
        float4 fc = s_fb[k][2];
        #pragma unroll
        for (int e = 0; e < EPT; ++e) {
            float t1 = tanh_fast(p[e]);
            float q1 = fmaf(fa.x, t1, q[e]);                        // q + a_e*tanh(p)
            float q2 = fmaf(fa.y, q1, fmaf(fa.z, p[e], fa.w));      // row0 of Me affine
            float t2 = tanh_fast(q2);
            float nq = fmaf(fb.w, t2, fmaf(fb.x, q1, fmaf(fb.y, p[e], fb.z)));
            float np = fmaf(fc.w, t2, fmaf(fc.x, q1, fmaf(fc.y, p[e], fc.z)));
            q[e] = nq; p[e] = np;
        }
    }

    // (time reversal folded into k = N_BLK-1 inverse constants)

    // ---------------- inverse chain: 16 fused blocks (reverse order) ----------------
    #pragma unroll 4
    for (int k = N_BLK - 1; k >= 0; --k) {
        float4 ia = s_ib[k][0];
        float4 ib = s_ib[k][1];
        float4 ic = s_ib[k][2];
        #pragma unroll
        for (int e = 0; e < EPT; ++e) {
            float qp = fmaf(ia.x, q[e], fmaf(ia.y, p[e], ia.z));    // q' = row0 of Uo affine
            float t2 = tanh_fast(qp);
            float nq = fmaf(ib.w, t2, fmaf(ib.x, q[e], fmaf(ib.y, p[e], ib.z)));
            float np = fmaf(ic.w, t2, fmaf(ic.x, q[e], fmaf(ic.y, p[e], ic.z)));
            q[e] = fmaf(ia.w, tanh_fast(np), nq);                   // q'' - a_e*tanh(p'')
            p[e] = np;
        }
    }

    // output (signs already folded into constants)
    #pragma unroll
    for (int e = 0; e < EPT; ++e) {
        int idx = base + e * TPB;
        if (idx < n) {
            out[idx] = make_float2(q[e], p[e]);
        }
    }
}

extern "C" void kernel_launch(void* const* d_in, const int* in_sizes, int n_in,
                              void* d_out, int out_size)
{
    const float2* x     = (const float2*)d_in[0];
    const float*  act_w = (const float*)d_in[1];
    const float*  bias_b= (const float*)d_in[2];
    const float*  lin_w = (const float*)d_in[3];
    float2* out = (float2*)d_out;

    int n = in_sizes[0] / 2;   // number of (q,p) pairs

    int per_block = TPB * EPT;
    int blocks = (n + per_block - 1) / per_block;
    sympnet_kernel<<<blocks, TPB>>>(x, act_w, bias_b, lin_w, out, n);
}

// round 12
// speedup vs baseline: 1.0539x; 1.0539x over previous
#include <cuda_runtime.h>

#define N_LAYERS 32
#define N_BLK    16          // fused 2-layer blocks per chain
#define N_SUB    8
#define TPB      128
#define EPT      6

// Composed layer constants: [0..3*N_BLK) forward blocks, [3*N_BLK..6*N_BLK) inverse blocks.
__constant__ float4 c_all[6 * N_BLK];
__device__   float4 g_all[6 * N_BLK];

__device__ __forceinline__ float tanh_fast(float x) {
    float y;
    asm("tanh.approx.f32 %0, %1;" : "=f"(y) : "f"(x));
    return y;
}

// Compose layer i's (bias then 8 shears) into forward affine v' = M v + c.
__device__ __forceinline__ void compose_fwd(const float* bias_b, const float* lin_w,
                                            int i, float M[4], float c[2]) {
    float m00 = 1.f, m01 = 0.f, m10 = 0.f, m11 = 1.f;
    float c0 = bias_b[2 * i + 0];
    float c1 = bias_b[2 * i + 1];
    #pragma unroll
    for (int j = 0; j < N_SUB; ++j) {
        float w = lin_w[i * N_SUB + j];
        if ((j & 1) == 0) {          // q += w*p
            m00 = fmaf(w, m10, m00);
            m01 = fmaf(w, m11, m01);
            c0  = fmaf(w, c1,  c0);
        } else {                      // p += w*q
            m10 = fmaf(w, m00, m10);
            m11 = fmaf(w, m01, m11);
            c1  = fmaf(w, c0,  c1);
        }
    }
    M[0] = m00; M[1] = m01; M[2] = m10; M[3] = m11;
    c[0] = c0;  c[1] = c1;
}

// Inverse affine of layer i: v = U w + d (reversed negated shears; d = -bias).
__device__ __forceinline__ void compose_inv(const float* bias_b, const float* lin_w,
                                            int i, float U[4], float d[2]) {
    float u00 = 1.f, u01 = 0.f, u10 = 0.f, u11 = 1.f;
    #pragma unroll
    for (int j = N_SUB - 1; j >= 0; --j) {
        float w = lin_w[i * N_SUB + j];
        if ((j & 1) == 0) {          // q -= w*p
            u00 = fmaf(-w, u10, u00);
            u01 = fmaf(-w, u11, u01);
        } else {                      // p -= w*q
            u10 = fmaf(-w, u00, u10);
            u11 = fmaf(-w, u01, u11);
        }
    }
    U[0] = u00; U[1] = u01; U[2] = u10; U[3] = u11;
    d[0] = -bias_b[2 * i + 0];
    d[1] = -bias_b[2 * i + 1];
}

// One warp composes all fused-block constants into g_all.
__global__ void setup_kernel(const float* __restrict__ act_w,
                             const float* __restrict__ bias_b,
                             const float* __restrict__ lin_w)
{
    const int t = threadIdx.x;
    if (t < N_BLK) {
        const int k = t, i = 2 * k;
        float Me[4], ce[2], Mo[4], co[2];
        compose_fwd(bias_b, lin_w, i,     Me, ce);
        compose_fwd(bias_b, lin_w, i + 1, Mo, co);
        float a_e = act_w[i], a_o = act_w[i + 1];
        float A00 = Mo[0] * Me[0] + Mo[1] * Me[2];
        float A01 = Mo[0] * Me[1] + Mo[1] * Me[3];
        float A10 = Mo[2] * Me[0] + Mo[3] * Me[2];
        float A11 = Mo[2] * Me[1] + Mo[3] * Me[3];
        float b0  = Mo[0] * ce[0] + Mo[1] * ce[1] + co[0];
        float b1  = Mo[2] * ce[0] + Mo[3] * ce[1] + co[1];
        float ah0 = a_o * Mo[1];
        float ah1 = a_o * Mo[3];
        g_all[3 * k + 0] = make_float4(a_e, Me[0], Me[1], ce[0]);
        g_all[3 * k + 1] = make_float4(A00, A01, b0, ah0);
        g_all[3 * k + 2] = make_float4(A10, A11, b1, ah1);
    } else if (t < 2 * N_BLK) {
        const int k = t - N_BLK, i = 2 * k;
        float Ue[4], de[2], Uo[4], dd[2];
        compose_inv(bias_b, lin_w, i,     Ue, de);
        compose_inv(bias_b, lin_w, i + 1, Uo, dd);
        float a_e = act_w[i], a_o = act_w[i + 1];
        float B00 = Ue[0] * Uo[0] + Ue[1] * Uo[2];
        float B01 = Ue[0] * Uo[1] + Ue[1] * Uo[3];
        float B10 = Ue[2] * Uo[0] + Ue[3] * Uo[2];
        float B11 = Ue[2] * Uo[1] + Ue[3] * Uo[3];
        float e0  = Ue[0] * dd[0] + Ue[1] * dd[1] + de[0];
        float e1  = Ue[2] * dd[0] + Ue[3] * dd[1] + de[1];
        float ch0 = -a_o * Ue[1];
        float ch1 = -a_o * Ue[3];
        // sy: fold time-reversal (-p) into entry block (k = N_BLK-1)
        // so: fold final (-p) output into exit block (k = 0)
        float sy = (k == N_BLK - 1) ? -1.f : 1.f;
        float so = (k == 0)         ? -1.f : 1.f;
        g_all[3 * N_BLK + 3 * k + 0] = make_float4(Uo[0], sy * Uo[1], dd[0], so * -a_e);
        g_all[3 * N_BLK + 3 * k + 1] = make_float4(B00, sy * B01, e0, ch0);
        g_all[3 * N_BLK + 3 * k + 2] = make_float4(so * B10, so * sy * B11, so * e1, so * ch1);
    }
}

__global__ __launch_bounds__(TPB, 10)
void sympnet_kernel(const float2* __restrict__ x,
                    float2*       __restrict__ out,
                    int n)
{
    const int base = blockIdx.x * (TPB * EPT) + threadIdx.x;

    float q[EPT], p[EPT];
    #pragma unroll
    for (int e = 0; e < EPT; ++e) {
        int idx = base + e * TPB;
        if (idx < n) {
            float2 v = x[idx];
            q[e] = v.x; p[e] = v.y;
        } else {
            q[e] = 0.f; p[e] = 0.f;
        }
    }

    // ---------------- forward chain: 16 fused blocks ----------------
    #pragma unroll 4
    for (int k = 0; k < N_BLK; ++k) {
        float4 fa = c_all[3 * k + 0];
        float4 fb = c_all[3 * k + 1];
        float4 fc = c_all[3 * k + 2];
        #pragma unroll
        for (int e = 0; e < EPT; ++e) {
            float t1 = tanh_fast(p[e]);
            float q1 = fmaf(fa.x, t1, q[e]);                        // q + a_e*tanh(p)
            float q2 = fmaf(fa.y, q1, fmaf(fa.z, p[e], fa.w));      // row0 of Me affine
            float t2 = tanh_fast(q2);
            float nq = fmaf(fb.w, t2, fmaf(fb.x, q1, fmaf(fb.y, p[e], fb.z)));
            float np = fmaf(fc.w, t2, fmaf(fc.x, q1, fmaf(fc.y, p[e], fc.z)));
            q[e] = nq; p[e] = np;
        }
    }

    // (time reversal folded into k = N_BLK-1 inverse constants)

    // ---------------- inverse chain: 16 fused blocks (reverse order) ----------------
    #pragma unroll 4
    for (int k = N_BLK - 1; k >= 0; --k) {
        float4 ia = c_all[3 * N_BLK + 3 * k + 0];
        float4 ib = c_all[3 * N_BLK + 3 * k + 1];
        float4 ic = c_all[3 * N_BLK + 3 * k + 2];
        #pragma unroll
        for (int e = 0; e < EPT; ++e) {
            float qp = fmaf(ia.x, q[e], fmaf(ia.y, p[e], ia.z));    // q' = row0 of Uo affine
            float t2 = tanh_fast(qp);
            float nq = fmaf(ib.w, t2, fmaf(ib.x, q[e], fmaf(ib.y, p[e], ib.z)));
            float np = fmaf(ic.w, t2, fmaf(ic.x, q[e], fmaf(ic.y, p[e], ic.z)));
            q[e] = fmaf(ia.w, tanh_fast(np), nq);                   // q'' - a_e*tanh(p'')
            p[e] = np;
        }
    }

    // output (signs already folded into constants)
    #pragma unroll
    for (int e = 0; e < EPT; ++e) {
        int idx = base + e * TPB;
        if (idx < n) {
            out[idx] = make_float2(q[e], p[e]);
        }
    }
}

extern "C" void kernel_launch(void* const* d_in, const int* in_sizes, int n_in,
                              void* d_out, int out_size)
{
    const float2* x     = (const float2*)d_in[0];
    const float*  act_w = (const float*)d_in[1];
    const float*  bias_b= (const float*)d_in[2];
    const float*  lin_w = (const float*)d_in[3];
    float2* out = (float2*)d_out;

    int n = in_sizes[0] / 2;   // number of (q,p) pairs

    // 1. compose constants on device
    setup_kernel<<<1, 2 * N_BLK>>>(act_w, bias_b, lin_w);

    // 2. move them into constant memory (D2D async copy — graph-capturable)
    void* g_ptr = nullptr;
    cudaGetSymbolAddress(&g_ptr, g_all);
    cudaMemcpyToSymbolAsync(c_all, g_ptr, sizeof(float4) * 6 * N_BLK, 0,
                            cudaMemcpyDeviceToDevice, 0);

    // 3. main kernel
    int per_block = TPB * EPT;
    int blocks = (n + per_block - 1) / per_block;
    sympnet_kernel<<<blocks, TPB>>>(x, out, n);
}

// round 13
// speedup vs baseline: 1.0548x; 1.0009x over previous
#include <cuda_runtime.h>

#define N_LAYERS 32
#define N_BLK    16          // fused 2-layer blocks per chain
#define N_SUB    8
#define TPB      128
#define EPT      6

__device__ __forceinline__ float tanh_fast(float x) {
    float y;
    asm("tanh.approx.f32 %0, %1;" : "=f"(y) : "f"(x));
    return y;
}

// Compose layer i's (bias then 8 shears) into forward affine v' = M v + c.
__device__ __forceinline__ void compose_fwd(const float* bias_b, const float* lin_w,
                                            int i, float M[4], float c[2]) {
    float m00 = 1.f, m01 = 0.f, m10 = 0.f, m11 = 1.f;
    float c0 = bias_b[2 * i + 0];
    float c1 = bias_b[2 * i + 1];
    #pragma unroll
    for (int j = 0; j < N_SUB; ++j) {
        float w = lin_w[i * N_SUB + j];
        if ((j & 1) == 0) {          // q += w*p
            m00 = fmaf(w, m10, m00);
            m01 = fmaf(w, m11, m01);
            c0  = fmaf(w, c1,  c0);
        } else {                      // p += w*q
            m10 = fmaf(w, m00, m10);
            m11 = fmaf(w, m01, m11);
            c1  = fmaf(w, c0,  c1);
        }
    }
    M[0] = m00; M[1] = m01; M[2] = m10; M[3] = m11;
    c[0] = c0;  c[1] = c1;
}

// Inverse affine of layer i: v = U w + d (reversed negated shears; d = -bias).
__device__ __forceinline__ void compose_inv(const float* bias_b, const float* lin_w,
                                            int i, float U[4], float d[2]) {
    float u00 = 1.f, u01 = 0.f, u10 = 0.f, u11 = 1.f;
    #pragma unroll
    for (int j = N_SUB - 1; j >= 0; --j) {
        float w = lin_w[i * N_SUB + j];
        if ((j & 1) == 0) {          // q -= w*p
            u00 = fmaf(-w, u10, u00);
            u01 = fmaf(-w, u11, u01);
        } else {                      // p -= w*q
            u10 = fmaf(-w, u00, u10);
            u11 = fmaf(-w, u01, u11);
        }
    }
    U[0] = u00; U[1] = u01; U[2] = u10; U[3] = u11;
    d[0] = -bias_b[2 * i + 0];
    d[1] = -bias_b[2 * i + 1];
}

__global__ __launch_bounds__(TPB, 10)
void sympnet_kernel(const float2* __restrict__ x,
                    const float*  __restrict__ act_w,
                    const float*  __restrict__ bias_b,
                    const float*  __restrict__ lin_w,
                    float2*       __restrict__ out,
                    int n)
{
    // Fused 2-layer block constants (3 x float4 each):
    // fwd[k]: [0]={a_e, Me00, Me01, ce0}  [1]={A00,A01,b0,ah0}  [2]={A10,A11,b1,ah1}
    // inv[k]: [0]={Uo00, Uo01, do0, -a_e} [1]={B00,B01,e0,ch0}  [2]={B10,B11,e1,ch1}
    // Sign folds: k=N_BLK-1 absorbs the time-reversal p -> -p (negated .y coeffs);
    //             k=0 absorbs the final (q, -p) output (negated np row + ia.w).
    __shared__ float4 s_fb[N_BLK][3];
    __shared__ float4 s_ib[N_BLK][3];

    const int t = threadIdx.x;

    if (t < N_BLK) {
        const int k = t, i = 2 * k;
        float Me[4], ce[2], Mo[4], co[2];
        compose_fwd(bias_b, lin_w, i,     Me, ce);
        compose_fwd(bias_b, lin_w, i + 1, Mo, co);
        float a_e = act_w[i], a_o = act_w[i + 1];
        // A = Mo * Me ; b = Mo*ce + co ; ah = a_o * (Mo col-p)
        float A00 = Mo[0] * Me[0] + Mo[1] * Me[2];
        float A01 = Mo[0] * Me[1] + Mo[1] * Me[3];
        float A10 = Mo[2] * Me[0] + Mo[3] * Me[2];
        float A11 = Mo[2] * Me[1] + Mo[3] * Me[3];
        float b0  = Mo[0] * ce[0] + Mo[1] * ce[1] + co[0];
        float b1  = Mo[2] * ce[0] + Mo[3] * ce[1] + co[1];
        float ah0 = a_o * Mo[1];
        float ah1 = a_o * Mo[3];
        s_fb[k][0] = make_float4(a_e, Me[0], Me[1], ce[0]);
        s_fb[k][1] = make_float4(A00, A01, b0, ah0);
        s_fb[k][2] = make_float4(A10, A11, b1, ah1);
    } else if (t < 2 * N_BLK) {
        const int k = t - N_BLK, i = 2 * k;
        float Ue[4], de[2], Uo[4], dd[2];
        compose_inv(bias_b, lin_w, i,     Ue, de);
        compose_inv(bias_b, lin_w, i + 1, Uo, dd);
        float a_e = act_w[i], a_o = act_w[i + 1];
        // B = Ue * Uo ; e = Ue*do + de ; ch = -a_o * (Ue col-p)
        float B00 = Ue[0] * Uo[0] + Ue[1] * Uo[2];
        float B01 = Ue[0] * Uo[1] + Ue[1] * Uo[3];
        float B10 = Ue[2] * Uo[0] + Ue[3] * Uo[2];
        float B11 = Ue[2] * Uo[1] + Ue[3] * Uo[3];
        float e0  = Ue[0] * dd[0] + Ue[1] * dd[1] + de[0];
        float e1  = Ue[2] * dd[0] + Ue[3] * dd[1] + de[1];
        float ch0 = -a_o * Ue[1];
        float ch1 = -a_o * Ue[3];
        // sy: fold time-reversal (-p) into entry block (k = N_BLK-1)
        // so: fold final (-p) output into exit block (k = 0)
        float sy = (k == N_BLK - 1) ? -1.f : 1.f;
        float so = (k == 0)         ? -1.f : 1.f;
        s_ib[k][0] = make_float4(Uo[0], sy * Uo[1], dd[0], so * -a_e);
        s_ib[k][1] = make_float4(B00, sy * B01, e0, ch0);
        s_ib[k][2] = make_float4(so * B10, so * sy * B11, so * e1, so * ch1);
    }
    __syncthreads();

    const int base = blockIdx.x * (TPB * EPT) + t;

    float q[EPT], p[EPT];
    #pragma unroll
    for (int e = 0; e < EPT; ++e) {
        int idx = base + e * TPB;
        if (idx < n) {
            float2 v = x[idx];
            q[e] = v.x; p[e] = v.y;
        } else {
            q[e] = 0.f; p[e] = 0.f;
        }
    }

    // ---------------- forward chain: 16 fused blocks ----------------
    #pragma unroll 4
    for (int k = 0; k < N_BLK; ++k) {
        float4 fa = s_fb[k][0];
        float4 fb = s_fb[k][1];
        float4 fc = s_fb[k][2];
        #pragma unroll
        for (int e = 0; e < EPT; ++e) {
            float t1 = tanh_fast(p[e]);
            float q1 = fmaf(fa.x, t1, q[e]);                        // q + a_e*tanh(p)
            float q2 = fmaf(fa.y, q1, fmaf(fa.z, p[e], fa.w));      // row0 of Me affine
            float t2 = tanh_fast(q2);
            float nq = fmaf(fb.w, t2, fmaf(fb.x, q1, fmaf(fb.y, p[e], fb.z)));
            float np = fmaf(fc.w, t2, fmaf(fc.x, q1, fmaf(fc.y, p[e], fc.z)));
            q[e] = nq; p[e] = np;
        }
    }

    // (time reversal folded into k = N_BLK-1 inverse constants)

    // ---------------- inverse chain: 16 fused blocks (reverse order) ----------------
    #pragma unroll 4
    for (int k = N_BLK - 1; k >= 0; --k) {
        float4 ia = s_ib[k][0];
        float4 ib = s_ib[k][1];
        float4 ic = s_ib[k][2];
        #pragma unroll
        for (int e = 0; e < EPT; ++e) {
            float qp = fmaf(ia.x, q[e], fmaf(ia.y, p[e], ia.z));    // q' = row0 of Uo affine
            float t2 = tanh_fast(qp);
            float nq = fmaf(ib.w, t2, fmaf(ib.x, q[e], fmaf(ib.y, p[e], ib.z)));
            float np = fmaf(ic.w, t2, fmaf(ic.x, q[e], fmaf(ic.y, p[e], ic.z)));
            q[e] = fmaf(ia.w, tanh_fast(np), nq);                   // q'' - a_e*tanh(p'')
            p[e] = np;
        }
    }

    // output (signs already folded into constants)
    #pragma unroll
    for (int e = 0; e < EPT; ++e) {
        int idx = base + e * TPB;
        if (idx < n) {
            out[idx] = make_float2(q[e], p[e]);
        }
    }
}

extern "C" void kernel_launch(void* const* d_in, const int* in_sizes, int n_in,
                              void* d_out, int out_size)
{
    const float2* x     = (const float2*)d_in[0];
    const float*  act_w = (const float*)d_in[1];
    const float*  bias_b= (const float*)d_in[2];
    const float*  lin_w = (const float*)d_in[3];
    float2* out = (float2*)d_out;

    int n = in_sizes[0] / 2;   // number of (q,p) pairs

    int per_block = TPB * EPT;
    int blocks = (n + per_block - 1) / per_block;
    sympnet_kernel<<<blocks, TPB>>>(x, act_w, bias_b, lin_w, out, n);
}